// round 1
// baseline (speedup 1.0000x reference)
#include <cuda_runtime.h>
#include <cuda_bf16.h>

// BioTripletLoss: B=16384 rows, D=1024 fp32.
// pos = ||h+r-t||, neg = ||h+r-t[neg_idx]||
// dissim (rel==1): relu(0.6 - pos) + 0.5*exp(-pos)
// sim:             relu(pos - neg + 0.3) + 0.3*relu(0.1 - pos)
// out = mean over B.

#define BDIM 1024
#define DDIM 1024
#define NTHREADS 256

static constexpr float MARGIN = 0.3f;
static constexpr float MIN_POS_DIST = 0.1f;
static constexpr float PUSH_SCALE = 2.0f;

__global__ void zero_out_kernel(float* out) {
    out[0] = 0.0f;
}

__global__ __launch_bounds__(NTHREADS)
void triplet_loss_kernel(const float* __restrict__ h,
                         const float* __restrict__ t,
                         const float* __restrict__ r,
                         const int* __restrict__ relation_ids,
                         const int* __restrict__ neg_idx,
                         float* __restrict__ out,
                         int B) {
    const int row = blockIdx.x;
    const int tid = threadIdx.x;

    const int j = neg_idx[row];

    const float4* __restrict__ h4  = reinterpret_cast<const float4*>(h + (size_t)row * DDIM);
    const float4* __restrict__ r4  = reinterpret_cast<const float4*>(r + (size_t)row * DDIM);
    const float4* __restrict__ tp4 = reinterpret_cast<const float4*>(t + (size_t)row * DDIM);
    const float4* __restrict__ tn4 = reinterpret_cast<const float4*>(t + (size_t)j   * DDIM);

    // D/4 = 256 float4 per row == one per thread. Issue all 4 loads up front (MLP=4).
    float4 hv = h4[tid];
    float4 rv = r4[tid];
    float4 tv = tp4[tid];
    float4 nv = tn4[tid];

    float hr_x = hv.x + rv.x;
    float hr_y = hv.y + rv.y;
    float hr_z = hv.z + rv.z;
    float hr_w = hv.w + rv.w;

    float dpx = hr_x - tv.x, dpy = hr_y - tv.y, dpz = hr_z - tv.z, dpw = hr_w - tv.w;
    float dnx = hr_x - nv.x, dny = hr_y - nv.y, dnz = hr_z - nv.z, dnw = hr_w - nv.w;

    float pos_sq = dpx*dpx + dpy*dpy + dpz*dpz + dpw*dpw;
    float neg_sq = dnx*dnx + dny*dny + dnz*dnz + dnw*dnw;

    // Warp reduce (both accumulators)
    #pragma unroll
    for (int off = 16; off > 0; off >>= 1) {
        pos_sq += __shfl_xor_sync(0xFFFFFFFFu, pos_sq, off);
        neg_sq += __shfl_xor_sync(0xFFFFFFFFu, neg_sq, off);
    }

    // Block reduce across 8 warps
    __shared__ float s_pos[NTHREADS / 32];
    __shared__ float s_neg[NTHREADS / 32];
    const int lane = tid & 31;
    const int wid = tid >> 5;
    if (lane == 0) {
        s_pos[wid] = pos_sq;
        s_neg[wid] = neg_sq;
    }
    __syncthreads();

    if (tid == 0) {
        float ps = 0.0f, ns = 0.0f;
        #pragma unroll
        for (int w = 0; w < NTHREADS / 32; w++) {
            ps += s_pos[w];
            ns += s_neg[w];
        }
        float pos_dist = sqrtf(ps);
        float neg_dist = sqrtf(ns);

        float loss;
        if (relation_ids[row] == 1) {
            float curr_margin = MARGIN * PUSH_SCALE;           // 0.6
            loss = fmaxf(curr_margin - pos_dist, 0.0f) + 0.5f * expf(-pos_dist);
        } else {
            loss = fmaxf(pos_dist - neg_dist + MARGIN, 0.0f)
                 + 0.3f * fmaxf(MIN_POS_DIST - pos_dist, 0.0f);
        }
        atomicAdd(out, loss * (1.0f / (float)B));
    }
}

extern "C" void kernel_launch(void* const* d_in, const int* in_sizes, int n_in,
                              void* d_out, int out_size) {
    const float* h = (const float*)d_in[0];
    const float* t = (const float*)d_in[1];
    const float* r = (const float*)d_in[2];
    const int* relation_ids = (const int*)d_in[3];
    const int* neg_idx = (const int*)d_in[4];
    float* out = (float*)d_out;

    const int B = in_sizes[3];  // element count of relation_ids

    zero_out_kernel<<<1, 1>>>(out);
    triplet_loss_kernel<<<B, NTHREADS>>>(h, t, r, relation_ids, neg_idx, out, B);
}

// round 3
// speedup vs baseline: 1.0585x; 1.0585x over previous
#include <cuda_runtime.h>
#include <cuda_bf16.h>

// BioTripletLoss: B=16384 rows, D=1024 fp32.
// pos = ||h+r-t||, neg = ||h+r-t[neg_idx]||
// dissim (rel==1): relu(0.6 - pos) + 0.5*exp(-pos)
// sim:             relu(pos - neg + 0.3) + 0.3*relu(0.1 - pos)
// out = mean over B.
//
// R3: warp-per-row + L2 eviction hints via 256-bit loads (sm_103a requires
// .v8.b32 for inline evict_first/evict_last qualifiers).
//   h, r  -> evict_first (single-use streams)
//   t     -> evict_last  (64 MiB, fits in L2; reused by gather)

#define DDIM 1024
#define NTHREADS 256
#define WARPS_PER_CTA (NTHREADS / 32)
// v8 load = 8 floats per lane; 1024 floats / (32 lanes * 8) = 4 iters/stream
#define ITERS 4

static constexpr float MARGIN = 0.3f;
static constexpr float MIN_POS_DIST = 0.1f;
static constexpr float PUSH_SCALE = 2.0f;

__global__ void zero_out_kernel(float* out) {
    out[0] = 0.0f;
}

struct f8 { float a0,a1,a2,a3,a4,a5,a6,a7; };

// Streaming 32B load: bias toward immediate eviction (single-use data).
__device__ __forceinline__ f8 ld_stream8(const float* p) {
    f8 v;
    asm("ld.global.nc.L2::evict_first.v8.b32 {%0,%1,%2,%3,%4,%5,%6,%7}, [%8];"
        : "=f"(v.a0), "=f"(v.a1), "=f"(v.a2), "=f"(v.a3),
          "=f"(v.a4), "=f"(v.a5), "=f"(v.a6), "=f"(v.a7)
        : "l"(p));
    return v;
}

// Resident 32B load: bias toward retention in L2 (t reused by gather).
__device__ __forceinline__ f8 ld_keep8(const float* p) {
    f8 v;
    asm("ld.global.nc.L2::evict_last.v8.b32 {%0,%1,%2,%3,%4,%5,%6,%7}, [%8];"
        : "=f"(v.a0), "=f"(v.a1), "=f"(v.a2), "=f"(v.a3),
          "=f"(v.a4), "=f"(v.a5), "=f"(v.a6), "=f"(v.a7)
        : "l"(p));
    return v;
}

__global__ __launch_bounds__(NTHREADS, 4)
void triplet_loss_kernel(const float* __restrict__ h,
                         const float* __restrict__ t,
                         const float* __restrict__ r,
                         const int* __restrict__ relation_ids,
                         const int* __restrict__ neg_idx,
                         float* __restrict__ out,
                         int B) {
    const int warp = threadIdx.x >> 5;
    const int lane = threadIdx.x & 31;
    const int row  = blockIdx.x * WARPS_PER_CTA + warp;

    const int j = __ldg(&neg_idx[row]);   // lane-uniform -> broadcast

    const float* __restrict__ hp = h + (size_t)row * DDIM;
    const float* __restrict__ rp = r + (size_t)row * DDIM;
    const float* __restrict__ tp = t + (size_t)row * DDIM;
    const float* __restrict__ np = t + (size_t)j   * DDIM;

    float pos_sq = 0.0f;
    float neg_sq = 0.0f;

    #pragma unroll
    for (int k = 0; k < ITERS; k++) {
        // lane-contiguous 32B chunks; warp covers 1024B per stream per iter
        const int off = (k * 32 + lane) * 8;
        f8 hv = ld_stream8(hp + off);
        f8 rv = ld_stream8(rp + off);
        f8 tv = ld_keep8(tp + off);
        f8 nv = ld_keep8(np + off);

        float hr0 = hv.a0 + rv.a0, hr1 = hv.a1 + rv.a1;
        float hr2 = hv.a2 + rv.a2, hr3 = hv.a3 + rv.a3;
        float hr4 = hv.a4 + rv.a4, hr5 = hv.a5 + rv.a5;
        float hr6 = hv.a6 + rv.a6, hr7 = hv.a7 + rv.a7;

        float d;
        d = hr0 - tv.a0; pos_sq += d*d;
        d = hr1 - tv.a1; pos_sq += d*d;
        d = hr2 - tv.a2; pos_sq += d*d;
        d = hr3 - tv.a3; pos_sq += d*d;
        d = hr4 - tv.a4; pos_sq += d*d;
        d = hr5 - tv.a5; pos_sq += d*d;
        d = hr6 - tv.a6; pos_sq += d*d;
        d = hr7 - tv.a7; pos_sq += d*d;

        d = hr0 - nv.a0; neg_sq += d*d;
        d = hr1 - nv.a1; neg_sq += d*d;
        d = hr2 - nv.a2; neg_sq += d*d;
        d = hr3 - nv.a3; neg_sq += d*d;
        d = hr4 - nv.a4; neg_sq += d*d;
        d = hr5 - nv.a5; neg_sq += d*d;
        d = hr6 - nv.a6; neg_sq += d*d;
        d = hr7 - nv.a7; neg_sq += d*d;
    }

    // Warp reduce (both accumulators)
    #pragma unroll
    for (int off = 16; off > 0; off >>= 1) {
        pos_sq += __shfl_xor_sync(0xFFFFFFFFu, pos_sq, off);
        neg_sq += __shfl_xor_sync(0xFFFFFFFFu, neg_sq, off);
    }

    if (lane == 0) {
        float pos_dist = sqrtf(pos_sq);
        float neg_dist = sqrtf(neg_sq);

        float loss;
        if (__ldg(&relation_ids[row]) == 1) {
            float curr_margin = MARGIN * PUSH_SCALE;           // 0.6
            loss = fmaxf(curr_margin - pos_dist, 0.0f) + 0.5f * expf(-pos_dist);
        } else {
            loss = fmaxf(pos_dist - neg_dist + MARGIN, 0.0f)
                 + 0.3f * fmaxf(MIN_POS_DIST - pos_dist, 0.0f);
        }
        atomicAdd(out, loss * (1.0f / (float)B));
    }
}

extern "C" void kernel_launch(void* const* d_in, const int* in_sizes, int n_in,
                              void* d_out, int out_size) {
    const float* h = (const float*)d_in[0];
    const float* t = (const float*)d_in[1];
    const float* r = (const float*)d_in[2];
    const int* relation_ids = (const int*)d_in[3];
    const int* neg_idx = (const int*)d_in[4];
    float* out = (float*)d_out;

    const int B = in_sizes[3];  // element count of relation_ids

    zero_out_kernel<<<1, 1>>>(out);
    triplet_loss_kernel<<<B / WARPS_PER_CTA, NTHREADS>>>(h, t, r, relation_ids, neg_idx, out, B);
}

// round 4
// speedup vs baseline: 1.1728x; 1.1080x over previous
#include <cuda_runtime.h>
#include <cuda_bf16.h>

// BioTripletLoss: B=16384 rows, D=1024 fp32.
// pos = ||h+r-t||, neg = ||h+r-t[neg_idx]||
// dissim (rel==1): relu(0.6 - pos) + 0.5*exp(-pos)
// sim:             relu(pos - neg + 0.3) + 0.3*relu(0.1 - pos)
// out = mean over B.
//
// R4: CTA-per-row (R1 shape: low regs, high occupancy) + L2 eviction policy
// via createpolicy + ld.global.nc.L2::cache_hint.v4.f32 (legal on 128-bit
// loads, unlike the inline evict_* qualifier which needs v8).
//   h, r  -> evict_first (single-use streams)
//   t     -> evict_last  (64 MiB fits in 126 MB L2; reused by the gather)

#define DDIM 1024
#define NTHREADS 256

static constexpr float MARGIN = 0.3f;
static constexpr float MIN_POS_DIST = 0.1f;
static constexpr float PUSH_SCALE = 2.0f;

__global__ void zero_out_kernel(float* out) {
    out[0] = 0.0f;
}

__device__ __forceinline__ float4 ld_hint4(const float4* p, unsigned long long pol) {
    float4 v;
    asm("ld.global.nc.L2::cache_hint.v4.f32 {%0,%1,%2,%3}, [%4], %5;"
        : "=f"(v.x), "=f"(v.y), "=f"(v.z), "=f"(v.w)
        : "l"(p), "l"(pol));
    return v;
}

__global__ __launch_bounds__(NTHREADS)
void triplet_loss_kernel(const float* __restrict__ h,
                         const float* __restrict__ t,
                         const float* __restrict__ r,
                         const int* __restrict__ relation_ids,
                         const int* __restrict__ neg_idx,
                         float* __restrict__ out,
                         int B) {
    const int row = blockIdx.x;
    const int tid = threadIdx.x;

    unsigned long long pol_first, pol_last;
    asm("createpolicy.fractional.L2::evict_first.b64 %0, 1.0;" : "=l"(pol_first));
    asm("createpolicy.fractional.L2::evict_last.b64 %0, 1.0;"  : "=l"(pol_last));

    const int j = __ldg(&neg_idx[row]);

    const float4* __restrict__ h4  = reinterpret_cast<const float4*>(h) + (size_t)row * (DDIM / 4);
    const float4* __restrict__ r4  = reinterpret_cast<const float4*>(r) + (size_t)row * (DDIM / 4);
    const float4* __restrict__ tp4 = reinterpret_cast<const float4*>(t) + (size_t)row * (DDIM / 4);
    const float4* __restrict__ tn4 = reinterpret_cast<const float4*>(t) + (size_t)j   * (DDIM / 4);

    // D/4 = 256 float4 per row == one per thread; 4 independent loads (MLP=4).
    float4 hv = ld_hint4(h4 + tid, pol_first);
    float4 rv = ld_hint4(r4 + tid, pol_first);
    float4 tv = ld_hint4(tp4 + tid, pol_last);
    float4 nv = ld_hint4(tn4 + tid, pol_last);

    float hr_x = hv.x + rv.x;
    float hr_y = hv.y + rv.y;
    float hr_z = hv.z + rv.z;
    float hr_w = hv.w + rv.w;

    float dpx = hr_x - tv.x, dpy = hr_y - tv.y, dpz = hr_z - tv.z, dpw = hr_w - tv.w;
    float dnx = hr_x - nv.x, dny = hr_y - nv.y, dnz = hr_z - nv.z, dnw = hr_w - nv.w;

    float pos_sq = dpx*dpx + dpy*dpy + dpz*dpz + dpw*dpw;
    float neg_sq = dnx*dnx + dny*dny + dnz*dnz + dnw*dnw;

    // Warp reduce (both accumulators)
    #pragma unroll
    for (int off = 16; off > 0; off >>= 1) {
        pos_sq += __shfl_xor_sync(0xFFFFFFFFu, pos_sq, off);
        neg_sq += __shfl_xor_sync(0xFFFFFFFFu, neg_sq, off);
    }

    // Block reduce across 8 warps
    __shared__ float s_pos[NTHREADS / 32];
    __shared__ float s_neg[NTHREADS / 32];
    const int lane = tid & 31;
    const int wid = tid >> 5;
    if (lane == 0) {
        s_pos[wid] = pos_sq;
        s_neg[wid] = neg_sq;
    }
    __syncthreads();

    if (tid == 0) {
        float ps = 0.0f, ns = 0.0f;
        #pragma unroll
        for (int w = 0; w < NTHREADS / 32; w++) {
            ps += s_pos[w];
            ns += s_neg[w];
        }
        float pos_dist = sqrtf(ps);
        float neg_dist = sqrtf(ns);

        float loss;
        if (__ldg(&relation_ids[row]) == 1) {
            float curr_margin = MARGIN * PUSH_SCALE;           // 0.6
            loss = fmaxf(curr_margin - pos_dist, 0.0f) + 0.5f * expf(-pos_dist);
        } else {
            loss = fmaxf(pos_dist - neg_dist + MARGIN, 0.0f)
                 + 0.3f * fmaxf(MIN_POS_DIST - pos_dist, 0.0f);
        }
        atomicAdd(out, loss * (1.0f / (float)B));
    }
}

extern "C" void kernel_launch(void* const* d_in, const int* in_sizes, int n_in,
                              void* d_out, int out_size) {
    const float* h = (const float*)d_in[0];
    const float* t = (const float*)d_in[1];
    const float* r = (const float*)d_in[2];
    const int* relation_ids = (const int*)d_in[3];
    const int* neg_idx = (const int*)d_in[4];
    float* out = (float*)d_out;

    const int B = in_sizes[3];  // element count of relation_ids

    zero_out_kernel<<<1, 1>>>(out);
    triplet_loss_kernel<<<B, NTHREADS>>>(h, t, r, relation_ids, neg_idx, out, B);
}

// round 5
// speedup vs baseline: 1.1803x; 1.0063x over previous
#include <cuda_runtime.h>
#include <cuda_bf16.h>

// BioTripletLoss: B=16384 rows, D=1024 fp32.
// pos = ||h+r-t||, neg = ||h+r-t[neg_idx]||
// dissim (rel==1): relu(0.6 - pos) + 0.5*exp(-pos)
// sim:             relu(pos - neg + 0.3) + 0.3*relu(0.1 - pos)
// out = mean over B.
//
// R5: 2 rows per CTA, all 8 loads front-batched so row B's memory traffic
// overlaps row A's reduction tail (the R4 limiter: DRAM pipe drained during
// each CTA's barrier+reduce with only MLP=4). L2 policy hints kept from R4:
//   h, r  -> evict_first (single-use streams)
//   t     -> evict_last  (fits in L2; reused by the gather)

#define DDIM 1024
#define NTHREADS 256
#define ROWS_PER_CTA 2

static constexpr float MARGIN = 0.3f;
static constexpr float MIN_POS_DIST = 0.1f;
static constexpr float PUSH_SCALE = 2.0f;

__global__ void zero_out_kernel(float* out) {
    out[0] = 0.0f;
}

__device__ __forceinline__ float4 ld_hint4(const float4* p, unsigned long long pol) {
    float4 v;
    asm("ld.global.nc.L2::cache_hint.v4.f32 {%0,%1,%2,%3}, [%4], %5;"
        : "=f"(v.x), "=f"(v.y), "=f"(v.z), "=f"(v.w)
        : "l"(p), "l"(pol));
    return v;
}

__device__ __forceinline__ float per_sample_loss(float ps, float ns, int rel, float invB) {
    float pos_dist = sqrtf(ps);
    float neg_dist = sqrtf(ns);
    float loss;
    if (rel == 1) {
        loss = fmaxf(MARGIN * PUSH_SCALE - pos_dist, 0.0f) + 0.5f * expf(-pos_dist);
    } else {
        loss = fmaxf(pos_dist - neg_dist + MARGIN, 0.0f)
             + 0.3f * fmaxf(MIN_POS_DIST - pos_dist, 0.0f);
    }
    return loss * invB;
}

__global__ __launch_bounds__(NTHREADS)
void triplet_loss_kernel(const float* __restrict__ h,
                         const float* __restrict__ t,
                         const float* __restrict__ r,
                         const int* __restrict__ relation_ids,
                         const int* __restrict__ neg_idx,
                         float* __restrict__ out,
                         int B) {
    const int row0 = blockIdx.x * ROWS_PER_CTA;
    const int row1 = row0 + 1;
    const int tid = threadIdx.x;

    unsigned long long pol_first, pol_last;
    asm("createpolicy.fractional.L2::evict_first.b64 %0, 1.0;" : "=l"(pol_first));
    asm("createpolicy.fractional.L2::evict_last.b64 %0, 1.0;"  : "=l"(pol_last));

    const int j0 = __ldg(&neg_idx[row0]);
    const int j1 = __ldg(&neg_idx[row1]);

    const float4* __restrict__ h4 = reinterpret_cast<const float4*>(h);
    const float4* __restrict__ r4 = reinterpret_cast<const float4*>(r);
    const float4* __restrict__ t4 = reinterpret_cast<const float4*>(t);
    const int V = DDIM / 4;  // 256 float4 per row == one per thread

    // Front-batch all 8 loads (MLP = 8): row B's traffic overlaps row A's
    // math + reduce.
    float4 hv0 = ld_hint4(h4 + (size_t)row0 * V + tid, pol_first);
    float4 rv0 = ld_hint4(r4 + (size_t)row0 * V + tid, pol_first);
    float4 tv0 = ld_hint4(t4 + (size_t)row0 * V + tid, pol_last);
    float4 nv0 = ld_hint4(t4 + (size_t)j0   * V + tid, pol_last);
    float4 hv1 = ld_hint4(h4 + (size_t)row1 * V + tid, pol_first);
    float4 rv1 = ld_hint4(r4 + (size_t)row1 * V + tid, pol_first);
    float4 tv1 = ld_hint4(t4 + (size_t)row1 * V + tid, pol_last);
    float4 nv1 = ld_hint4(t4 + (size_t)j1   * V + tid, pol_last);

    float hx, hy, hz, hw, d;

    // Row 0
    hx = hv0.x + rv0.x; hy = hv0.y + rv0.y; hz = hv0.z + rv0.z; hw = hv0.w + rv0.w;
    float ps0 = 0.0f, ns0 = 0.0f;
    d = hx - tv0.x; ps0 += d*d;  d = hy - tv0.y; ps0 += d*d;
    d = hz - tv0.z; ps0 += d*d;  d = hw - tv0.w; ps0 += d*d;
    d = hx - nv0.x; ns0 += d*d;  d = hy - nv0.y; ns0 += d*d;
    d = hz - nv0.z; ns0 += d*d;  d = hw - nv0.w; ns0 += d*d;

    // Row 1
    hx = hv1.x + rv1.x; hy = hv1.y + rv1.y; hz = hv1.z + rv1.z; hw = hv1.w + rv1.w;
    float ps1 = 0.0f, ns1 = 0.0f;
    d = hx - tv1.x; ps1 += d*d;  d = hy - tv1.y; ps1 += d*d;
    d = hz - tv1.z; ps1 += d*d;  d = hw - tv1.w; ps1 += d*d;
    d = hx - nv1.x; ns1 += d*d;  d = hy - nv1.y; ns1 += d*d;
    d = hz - nv1.z; ns1 += d*d;  d = hw - nv1.w; ns1 += d*d;

    // Warp reduce all four accumulators
    #pragma unroll
    for (int off = 16; off > 0; off >>= 1) {
        ps0 += __shfl_xor_sync(0xFFFFFFFFu, ps0, off);
        ns0 += __shfl_xor_sync(0xFFFFFFFFu, ns0, off);
        ps1 += __shfl_xor_sync(0xFFFFFFFFu, ps1, off);
        ns1 += __shfl_xor_sync(0xFFFFFFFFu, ns1, off);
    }

    // Block reduce across 8 warps, one barrier for both rows
    __shared__ float s_ps0[NTHREADS / 32], s_ns0[NTHREADS / 32];
    __shared__ float s_ps1[NTHREADS / 32], s_ns1[NTHREADS / 32];
    const int lane = tid & 31;
    const int wid = tid >> 5;
    if (lane == 0) {
        s_ps0[wid] = ps0; s_ns0[wid] = ns0;
        s_ps1[wid] = ps1; s_ns1[wid] = ns1;
    }
    __syncthreads();

    const float invB = 1.0f / (float)B;
    if (tid == 0) {
        float ps = 0.0f, ns = 0.0f;
        #pragma unroll
        for (int w = 0; w < NTHREADS / 32; w++) { ps += s_ps0[w]; ns += s_ns0[w]; }
        atomicAdd(out, per_sample_loss(ps, ns, __ldg(&relation_ids[row0]), invB));
    } else if (tid == 32) {
        float ps = 0.0f, ns = 0.0f;
        #pragma unroll
        for (int w = 0; w < NTHREADS / 32; w++) { ps += s_ps1[w]; ns += s_ns1[w]; }
        atomicAdd(out, per_sample_loss(ps, ns, __ldg(&relation_ids[row1]), invB));
    }
}

extern "C" void kernel_launch(void* const* d_in, const int* in_sizes, int n_in,
                              void* d_out, int out_size) {
    const float* h = (const float*)d_in[0];
    const float* t = (const float*)d_in[1];
    const float* r = (const float*)d_in[2];
    const int* relation_ids = (const int*)d_in[3];
    const int* neg_idx = (const int*)d_in[4];
    float* out = (float*)d_out;

    const int B = in_sizes[3];  // element count of relation_ids

    zero_out_kernel<<<1, 1>>>(out);
    triplet_loss_kernel<<<B / ROWS_PER_CTA, NTHREADS>>>(h, t, r, relation_ids, neg_idx, out, B);
}